// round 2
// baseline (speedup 1.0000x reference)
#include <cuda_runtime.h>

#define BATCH 256
#define FEAT  512
#define NT    128          // threads per block; FEAT/4 float4s per row == NT

// Scratch (allocation-free rule: __device__ globals)
__device__ float g_dist[BATCH];   // per-row squared distance
__device__ float g_lse[BATCH];    // per-row logsumexp(feats)

// Kernel 1: one block per batch row.
// Computes dist_b = ||f_b - c_{y_b}||^2 and lse_b = logsumexp(feats[b,:]).
// Each thread owns exactly one float4 of the 512-wide row.
__global__ void __launch_bounds__(NT) cl_row_kernel(
    const float* __restrict__ feats,
    const float* __restrict__ centers,
    const int*   __restrict__ labels)
{
    const int b = blockIdx.x;
    const int t = threadIdx.x;

    const float4* f4 = reinterpret_cast<const float4*>(feats) + (size_t)b * (FEAT / 4);
    const long long lab = labels[b];
    const float4* c4 = reinterpret_cast<const float4*>(centers) + (long long)lab * (FEAT / 4);

    float4 f = f4[t];
    float4 c = c4[t];

    float d0 = f.x - c.x, d1 = f.y - c.y, d2 = f.z - c.z, d3 = f.w - c.w;
    float dist = d0 * d0 + d1 * d1 + d2 * d2 + d3 * d3;

    float mx = fmaxf(fmaxf(f.x, f.y), fmaxf(f.z, f.w));

    __shared__ float s_a[NT];
    __shared__ float s_b[NT];

    // --- block max reduce (deterministic fixed tree) ---
    s_a[t] = mx;
    __syncthreads();
    #pragma unroll
    for (int s = NT / 2; s > 0; s >>= 1) {
        if (t < s) s_a[t] = fmaxf(s_a[t], s_a[t + s]);
        __syncthreads();
    }
    const float rowmax = s_a[0];
    __syncthreads();

    float e = __expf(f.x - rowmax) + __expf(f.y - rowmax)
            + __expf(f.z - rowmax) + __expf(f.w - rowmax);

    // --- block sum reduce: dist and expsum together ---
    s_a[t] = dist;
    s_b[t] = e;
    __syncthreads();
    #pragma unroll
    for (int s = NT / 2; s > 0; s >>= 1) {
        if (t < s) {
            s_a[t] += s_a[t + s];
            s_b[t] += s_b[t + s];
        }
        __syncthreads();
    }

    if (t == 0) {
        g_dist[b] = s_a[0];
        g_lse[b]  = rowmax + __logf(s_b[0]);
    }
}

// Kernel 2: one block per batch row. Each block deterministically re-reduces
// the 256-entry dist array (cheap, fixed tree), then writes
// out[b,j] = total + feats[b,j] - lse[b].
__global__ void __launch_bounds__(NT) cl_out_kernel(
    const float* __restrict__ feats,
    float* __restrict__ out)
{
    const int b = blockIdx.x;
    const int t = threadIdx.x;

    __shared__ float s_a[NT];
    // BATCH == 2*NT: each thread folds two entries first
    s_a[t] = g_dist[t] + g_dist[t + NT];
    __syncthreads();
    #pragma unroll
    for (int s = NT / 2; s > 0; s >>= 1) {
        if (t < s) s_a[t] += s_a[t + s];
        __syncthreads();
    }
    const float total = s_a[0];
    const float lse   = g_lse[b];
    const float add   = total - lse;

    const float4* f4 = reinterpret_cast<const float4*>(feats) + (size_t)b * (FEAT / 4);
    float4* o4 = reinterpret_cast<float4*>(out) + (size_t)b * (FEAT / 4);

    float4 f = f4[t];
    float4 o;
    o.x = f.x + add;
    o.y = f.y + add;
    o.z = f.z + add;
    o.w = f.w + add;
    o4[t] = o;
}

extern "C" void kernel_launch(void* const* d_in, const int* in_sizes, int n_in,
                              void* d_out, int out_size)
{
    const float* feats   = (const float*)d_in[0];
    const float* centers = (const float*)d_in[1];
    const int*   labels  = (const int*)d_in[2];
    float* out = (float*)d_out;

    cl_row_kernel<<<BATCH, NT>>>(feats, centers, labels);
    cl_out_kernel<<<BATCH, NT>>>(feats, out);
}